// round 1
// baseline (speedup 1.0000x reference)
#include <cuda_runtime.h>

// EdgewiseReduce: out[n, :] = sum over edges e with edge_center[e] == n of edge_feat[e, :]
// edge_center (= edge_index[0]) is SORTED ascending -> node-centric segmented sum,
// no atomics, no memset (every node row is written exactly once).
//
// Inputs (metadata order):
//   d_in[0] = edge_index  [2, E]  int64 (or int32 if x64 disabled) -- runtime-detected
//   d_in[1] = edge_feat   [E, 64] float32
//   d_in[2] = node_types  [N, 1]  int  (only used implicitly via out_size)
// Output: [N, 64] float32

#define D_FEAT 64
#define VEC 4                    // float4
#define LANES (D_FEAT / VEC)     // 16 lanes per node
#define BLOCK_THREADS 256
#define GROUPS_PER_BLOCK (BLOCK_THREADS / LANES)  // 16 nodes per CTA

// Load edge_center[i] under either dtype interpretation.
__device__ __forceinline__ int ldc(const void* __restrict__ p, int i, bool is64) {
    if (is64) return (int)__ldg(((const long long*)p) + i);
    return __ldg(((const int*)p) + i);
}

__global__ void __launch_bounds__(BLOCK_THREADS)
edgewise_reduce_kernel(const void* __restrict__ edge_index,
                       const float4* __restrict__ feat,   // [E * LANES]
                       float4* __restrict__ out,          // [N * LANES]
                       int E, int N)
{
    // ---- runtime dtype detection (shared across block) ----
    // Reading the [2,E] index buffer as int64 at indices < E is always in
    // bounds (buffer is >= 8E bytes either way). If the data is really int32,
    // an int64 read combines two adjacent indices -> value >= 2^32 >> N with
    // overwhelming probability across 3 probes.
    __shared__ int s_is64;
    if (threadIdx.x == 0) {
        const long long* p64 = (const long long*)edge_index;
        unsigned long long v0 = (unsigned long long)p64[E / 3];
        unsigned long long v1 = (unsigned long long)p64[E / 2];
        unsigned long long v2 = (unsigned long long)p64[E - 1];
        unsigned long long nn = (unsigned long long)N;
        s_is64 = (v0 < nn && v1 < nn && v2 < nn) ? 1 : 0;
    }
    __syncthreads();
    const bool is64 = (s_is64 != 0);

    const int lane  = threadIdx.x & (LANES - 1);
    const int group = threadIdx.x / LANES;
    const int node  = blockIdx.x * GROUPS_PER_BLOCK + group;
    if (node >= N) return;

    // lower_bound(node): first i with center[i] >= node
    int lo = 0, hi = E;
    while (lo < hi) {
        int mid = (lo + hi) >> 1;
        if (ldc(edge_index, mid, is64) < node) lo = mid + 1; else hi = mid;
    }
    const int start = lo;
    // lower_bound(node + 1): continue from 'start'
    hi = E;
    while (lo < hi) {
        int mid = (lo + hi) >> 1;
        if (ldc(edge_index, mid, is64) < node + 1) lo = mid + 1; else hi = mid;
    }
    const int end = lo;

    // ---- segmented sum: 16 lanes x float4 = full 64-float row per edge ----
    float4 acc = make_float4(0.f, 0.f, 0.f, 0.f);
    int e = start;
    // 4-deep unroll for memory-level parallelism
    for (; e + 4 <= end; e += 4) {
        float4 a = __ldg(&feat[(long long)(e + 0) * LANES + lane]);
        float4 b = __ldg(&feat[(long long)(e + 1) * LANES + lane]);
        float4 c = __ldg(&feat[(long long)(e + 2) * LANES + lane]);
        float4 d = __ldg(&feat[(long long)(e + 3) * LANES + lane]);
        acc.x += (a.x + b.x) + (c.x + d.x);
        acc.y += (a.y + b.y) + (c.y + d.y);
        acc.z += (a.z + b.z) + (c.z + d.z);
        acc.w += (a.w + b.w) + (c.w + d.w);
    }
    for (; e < end; ++e) {
        float4 a = __ldg(&feat[(long long)e * LANES + lane]);
        acc.x += a.x; acc.y += a.y; acc.z += a.z; acc.w += a.w;
    }

    out[(long long)node * LANES + lane] = acc;
}

extern "C" void kernel_launch(void* const* d_in, const int* in_sizes, int n_in,
                              void* d_out, int out_size)
{
    const void*   edge_index = d_in[0];
    const float4* feat       = (const float4*)d_in[1];
    float4*       out        = (float4*)d_out;

    const int E = in_sizes[1] / D_FEAT;   // edge_feat element count / 64
    const int N = out_size / D_FEAT;      // output rows

    const int grid = (N + GROUPS_PER_BLOCK - 1) / GROUPS_PER_BLOCK;
    edgewise_reduce_kernel<<<grid, BLOCK_THREADS>>>(edge_index, feat, out, E, N);
}

// round 2
// speedup vs baseline: 1.2948x; 1.2948x over previous
#include <cuda_runtime.h>

// EdgewiseReduce: out[n, :] = sum_{e : edge_center[e] == n} edge_feat[e, :]
// edge_center (= edge_index[0]) is SORTED ascending.
//
// Two-pass scheme:
//   Pass 1 (build_offsets): edge-parallel CSR row_offsets from the sorted key
//                           array -> g_offsets[0..N], g_offsets[n] = first edge
//                           with center >= n. Handles empty nodes and tail.
//   Pass 2 (reduce): one 16-lane group per node; float4-vectorized register
//                    accumulation over [offsets[n], offsets[n+1]); single
//                    coalesced store. No atomics, no memset, no search.
//
// Inputs (metadata order):
//   d_in[0] = edge_index  [2, E]  int64 (or int32; runtime-detected)
//   d_in[1] = edge_feat   [E, 64] float32
//   d_in[2] = node_types  [N, 1]
// Output: [N, 64] float32

#define D_FEAT 64
#define LANES 16                               // 16 lanes x float4 = 64 floats
#define BLOCK_THREADS 256
#define GROUPS_PER_BLOCK (BLOCK_THREADS / LANES)
#define MAX_NODES_P1 (1 << 21)                 // scratch capacity (N+1 used)

__device__ int g_offsets[MAX_NODES_P1];

__device__ __forceinline__ int ldc(const void* __restrict__ p, int i, bool is64) {
    if (is64) return (int)__ldg(((const long long*)p) + i);
    return __ldg(((const int*)p) + i);
}

// ---------------- Pass 1: CSR offsets from sorted keys ----------------
__global__ void __launch_bounds__(256)
build_offsets_kernel(const void* __restrict__ edge_index, int E, int N)
{
    // dtype detection: int64 read of an int32 buffer fuses two indices ->
    // value >= 2^32 >> N with overwhelming probability across 3 probes.
    __shared__ int s_is64;
    if (threadIdx.x == 0) {
        const long long* p64 = (const long long*)edge_index;
        unsigned long long v0 = (unsigned long long)p64[E / 3];
        unsigned long long v1 = (unsigned long long)p64[E / 2];
        unsigned long long v2 = (unsigned long long)p64[E - 1];
        unsigned long long nn = (unsigned long long)N;
        s_is64 = (v0 < nn && v1 < nn && v2 < nn) ? 1 : 0;
    }
    __syncthreads();
    const bool is64 = (s_is64 != 0);

    const int e = blockIdx.x * blockDim.x + threadIdx.x;
    if (e >= E) return;

    const int c  = ldc(edge_index, e, is64);
    const int cp = (e == 0) ? -1 : ldc(edge_index, e - 1, is64);

    // Segment transition at e: nodes (cp, c] all start here.
    for (int n = cp + 1; n <= c; ++n) g_offsets[n] = e;

    // Tail: nodes beyond the last key have empty ranges ending at E.
    if (e == E - 1) {
        for (int n = c + 1; n <= N; ++n) g_offsets[n] = E;
    }
}

// ---------------- Pass 2: node-centric segmented sum ----------------
__global__ void __launch_bounds__(BLOCK_THREADS)
edgewise_reduce_kernel(const float4* __restrict__ feat,   // [E * LANES]
                       float4* __restrict__ out,          // [N * LANES]
                       int N)
{
    const int lane  = threadIdx.x & (LANES - 1);
    const int group = threadIdx.x / LANES;
    const int node  = blockIdx.x * GROUPS_PER_BLOCK + group;
    if (node >= N) return;

    const int start = g_offsets[node];
    const int end   = g_offsets[node + 1];

    float4 acc = make_float4(0.f, 0.f, 0.f, 0.f);
    int e = start;
    #pragma unroll 1
    for (; e + 4 <= end; e += 4) {
        float4 a = __ldg(&feat[(long long)(e + 0) * LANES + lane]);
        float4 b = __ldg(&feat[(long long)(e + 1) * LANES + lane]);
        float4 c = __ldg(&feat[(long long)(e + 2) * LANES + lane]);
        float4 d = __ldg(&feat[(long long)(e + 3) * LANES + lane]);
        acc.x += (a.x + b.x) + (c.x + d.x);
        acc.y += (a.y + b.y) + (c.y + d.y);
        acc.z += (a.z + b.z) + (c.z + d.z);
        acc.w += (a.w + b.w) + (c.w + d.w);
    }
    for (; e < end; ++e) {
        float4 a = __ldg(&feat[(long long)e * LANES + lane]);
        acc.x += a.x; acc.y += a.y; acc.z += a.z; acc.w += a.w;
    }

    out[(long long)node * LANES + lane] = acc;
}

extern "C" void kernel_launch(void* const* d_in, const int* in_sizes, int n_in,
                              void* d_out, int out_size)
{
    const void*   edge_index = d_in[0];
    const float4* feat       = (const float4*)d_in[1];
    float4*       out        = (float4*)d_out;

    const int E = in_sizes[1] / D_FEAT;
    const int N = out_size / D_FEAT;

    build_offsets_kernel<<<(E + 255) / 256, 256>>>(edge_index, E, N);

    const int grid = (N + GROUPS_PER_BLOCK - 1) / GROUPS_PER_BLOCK;
    edgewise_reduce_kernel<<<grid, BLOCK_THREADS>>>(feat, out, N);
}